// round 1
// baseline (speedup 1.0000x reference)
#include <cuda_runtime.h>
#include <cstdint>

// Problem shape (fixed by the dataset)
#define Bdim 4
#define Ldim 4096
#define Ddim 1024
#define Mrows (Bdim * Ldim)          // 16384
#define BLD ((size_t)Bdim * Ldim * Ddim)
#define NCHUNK 64
#define CLEN (Ldim / NCHUNK)         // 64

// ---------------- scratch (static device arrays; no allocation) -------------
__device__ float g_norm[(size_t)Mrows * Ddim];   // ctx_norm
__device__ float g_alpha[(size_t)Mrows * Ddim];  // raw alpha logits, then alphas
__device__ float g_x[(size_t)Mrows * Ddim];      // gated recurrence input x_t
__device__ float g_f[(size_t)Mrows * Ddim];      // fetched (scan output)
__device__ float g_Xagg[(size_t)Bdim * NCHUNK * Ddim];
__device__ float g_Aagg[(size_t)Bdim * NCHUNK * Ddim];
__device__ float g_carry[(size_t)Bdim * NCHUNK * Ddim];

__device__ __forceinline__ float sigmoidf_(float z) {
    return 1.0f / (1.0f + __expf(-z));
}

// ---------------- rmsnorm ----------------------------------------------------
__global__ void rms_kernel(const float* __restrict__ ctx,
                           const float* __restrict__ g,
                           float* __restrict__ o) {
    int row = blockIdx.x, tid = threadIdx.x;
    const float4* src = (const float4*)(ctx + (size_t)row * Ddim);
    float4 xv = src[tid];
    float ss = xv.x * xv.x + xv.y * xv.y + xv.z * xv.z + xv.w * xv.w;
#pragma unroll
    for (int off = 16; off > 0; off >>= 1)
        ss += __shfl_xor_sync(0xffffffffu, ss, off);
    __shared__ float ws[8];
    if ((tid & 31) == 0) ws[tid >> 5] = ss;
    __syncthreads();
    float tot = ws[0] + ws[1] + ws[2] + ws[3] + ws[4] + ws[5] + ws[6] + ws[7];
    float r = rsqrtf(tot * (1.0f / Ddim) + 1e-6f);
    float4 gv = ((const float4*)g)[tid];
    float4 ov = make_float4(xv.x * r * gv.x, xv.y * r * gv.y,
                            xv.z * r * gv.z, xv.w * r * gv.w);
    ((float4*)(o + (size_t)row * Ddim))[tid] = ov;
}

// ---------------- TF32 mma.sync GEMM -----------------------------------------
// C[M,N] = A[M,K] @ B[K,N]  (all row-major fp32, tf32 tensor-core compute)
// Block tile 128x128x16, 256 threads (8 warps as 4x2), warp tile 32x64.
// modes:
//   0: C = acc
//   1: C = aux2 + silu(acc + bias)                        (ctx residual GEMM)
//   2: gate epilogue:
//        a    = sigmoid(aux1 + bias2)   (aux1 = raw alpha logits, overwritten)
//        beta = silu(acc + bias)
//        C    = aux2 * beta * sqrt(max(1 - a^2, 1e-6))    (aux2 = v)
#define BM 128
#define BN 128
#define BKT 16
#define APAD 20
#define BPAD 136

__device__ __forceinline__ uint32_t f2tf(float f) {
    uint32_t u;
    asm("cvt.rna.tf32.f32 %0, %1;" : "=r"(u) : "f"(f));
    return u;
}

#define CP16(dst, src) \
    asm volatile("cp.async.cg.shared.global [%0], [%1], 16;\n" ::"r"(dst), "l"(src))

__global__ void __launch_bounds__(256) gemm_tf32_kernel(
    const float* __restrict__ A, const float* __restrict__ Bw,
    float* __restrict__ C, int M, int N, int K, int mode,
    const float* __restrict__ bias, const float* __restrict__ bias2,
    float* __restrict__ aux1, const float* __restrict__ aux2) {
    __shared__ float As[2][BM][APAD];
    __shared__ float Bs[2][BKT][BPAD];

    const int tid = threadIdx.x;
    const int warp = tid >> 5, lane = tid & 31;
    const int wm = warp >> 1, wn = warp & 1;
    const int gid = lane >> 2, tig = lane & 3;
    const int m0 = blockIdx.y * BM, n0 = blockIdx.x * BN;

    float acc[2][8][4];
#pragma unroll
    for (int i = 0; i < 2; i++)
#pragma unroll
        for (int j = 0; j < 8; j++)
#pragma unroll
            for (int k = 0; k < 4; k++) acc[i][j][k] = 0.0f;

    const int a_r = tid >> 2;            // 0..63
    const int a_c = (tid & 3) * 4;       // 0,4,8,12
    const int b_r = tid >> 5;            // 0..7
    const int b_c = (tid & 31) * 4;      // 0..124

    auto load_tile = [&](int kt, int buf) {
        int k0 = kt * BKT;
        {
            const float* s = A + (size_t)(m0 + a_r) * K + k0 + a_c;
            uint32_t d = (uint32_t)__cvta_generic_to_shared(&As[buf][a_r][a_c]);
            CP16(d, s);
            s += (size_t)64 * K;
            d = (uint32_t)__cvta_generic_to_shared(&As[buf][a_r + 64][a_c]);
            CP16(d, s);
        }
        {
            const float* s = Bw + (size_t)(k0 + b_r) * N + n0 + b_c;
            uint32_t d = (uint32_t)__cvta_generic_to_shared(&Bs[buf][b_r][b_c]);
            CP16(d, s);
            s += (size_t)8 * N;
            d = (uint32_t)__cvta_generic_to_shared(&Bs[buf][b_r + 8][b_c]);
            CP16(d, s);
        }
        asm volatile("cp.async.commit_group;\n");
    };

    const int KT = K / BKT;
    load_tile(0, 0);
    int buf = 0;
    for (int kt = 0; kt < KT; kt++) {
        asm volatile("cp.async.wait_group 0;\n");
        __syncthreads();
        if (kt + 1 < KT) load_tile(kt + 1, buf ^ 1);

#pragma unroll
        for (int ks = 0; ks < 2; ks++) {
            const int ko = ks * 8;
            uint32_t af[2][4], bf[8][2];
#pragma unroll
            for (int mf = 0; mf < 2; mf++) {
                int r = wm * 32 + mf * 16 + gid;
                af[mf][0] = f2tf(As[buf][r][ko + tig]);
                af[mf][1] = f2tf(As[buf][r + 8][ko + tig]);
                af[mf][2] = f2tf(As[buf][r][ko + tig + 4]);
                af[mf][3] = f2tf(As[buf][r + 8][ko + tig + 4]);
            }
#pragma unroll
            for (int nf = 0; nf < 8; nf++) {
                int c = wn * 64 + nf * 8 + gid;
                bf[nf][0] = f2tf(Bs[buf][ko + tig][c]);
                bf[nf][1] = f2tf(Bs[buf][ko + tig + 4][c]);
            }
#pragma unroll
            for (int mf = 0; mf < 2; mf++)
#pragma unroll
                for (int nf = 0; nf < 8; nf++) {
                    asm volatile(
                        "mma.sync.aligned.m16n8k8.row.col.f32.tf32.tf32.f32 "
                        "{%0,%1,%2,%3}, {%4,%5,%6,%7}, {%8,%9}, {%0,%1,%2,%3};\n"
                        : "+f"(acc[mf][nf][0]), "+f"(acc[mf][nf][1]),
                          "+f"(acc[mf][nf][2]), "+f"(acc[mf][nf][3])
                        : "r"(af[mf][0]), "r"(af[mf][1]), "r"(af[mf][2]),
                          "r"(af[mf][3]), "r"(bf[nf][0]), "r"(bf[nf][1]));
                }
        }
        buf ^= 1;
    }

// ---------------- epilogue ----------------
#pragma unroll
    for (int mf = 0; mf < 2; mf++) {
#pragma unroll
        for (int nf = 0; nf < 8; nf++) {
            int row = m0 + wm * 32 + mf * 16 + gid;
            int col = n0 + wn * 64 + nf * 8 + tig * 2;
#pragma unroll
            for (int h = 0; h < 2; h++) {
                int r = row + h * 8;
                size_t idx = (size_t)r * N + col;
                float v0 = acc[mf][nf][h * 2 + 0];
                float v1 = acc[mf][nf][h * 2 + 1];
                if (mode == 0) {
                    *(float2*)(C + idx) = make_float2(v0, v1);
                } else if (mode == 1) {
                    float z0 = v0 + bias[col], z1 = v1 + bias[col + 1];
                    float s0 = z0 * sigmoidf_(z0);
                    float s1 = z1 * sigmoidf_(z1);
                    *(float2*)(C + idx) =
                        make_float2(aux2[idx] + s0, aux2[idx + 1] + s1);
                } else {
                    float a0 = sigmoidf_(aux1[idx] + bias2[col]);
                    float a1 = sigmoidf_(aux1[idx + 1] + bias2[col + 1]);
                    float zb0 = v0 + bias[col], zb1 = v1 + bias[col + 1];
                    float be0 = zb0 * sigmoidf_(zb0);
                    float be1 = zb1 * sigmoidf_(zb1);
                    float w0 = sqrtf(fmaxf(1.0f - a0 * a0, 1e-6f));
                    float w1 = sqrtf(fmaxf(1.0f - a1 * a1, 1e-6f));
                    float x0 = aux2[idx] * be0 * w0;
                    float x1 = aux2[idx + 1] * be1 * w1;
                    *(float2*)(aux1 + idx) = make_float2(a0, a1);
                    *(float2*)(C + idx) = make_float2(x0, x1);
                }
            }
        }
    }
}

// ---------------- chunked linear recurrence (h_t = a_t h_{t-1} + x_t) --------
__global__ void scan_p1(const float* __restrict__ a, const float* __restrict__ x,
                        float* __restrict__ Xagg, float* __restrict__ Aagg) {
    int d = blockIdx.x * blockDim.x + threadIdx.x;
    int c = blockIdx.y, b = blockIdx.z;
    size_t base = ((size_t)b * Ldim + (size_t)c * CLEN) * Ddim + d;
    float X = 0.0f, A = 1.0f;
#pragma unroll 8
    for (int t = 0; t < CLEN; t++) {
        float at = a[base + (size_t)t * Ddim];
        float xt = x[base + (size_t)t * Ddim];
        X = fmaf(at, X, xt);
        A *= at;
    }
    size_t o = ((size_t)b * NCHUNK + c) * Ddim + d;
    Xagg[o] = X;
    Aagg[o] = A;
}

__global__ void scan_p2(const float* __restrict__ Xagg,
                        const float* __restrict__ Aagg,
                        float* __restrict__ carry) {
    int i = blockIdx.x * blockDim.x + threadIdx.x;  // 0 .. B*D
    int b = i / Ddim, d = i % Ddim;
    float h = 0.0f;
#pragma unroll 8
    for (int c = 0; c < NCHUNK; c++) {
        size_t o = ((size_t)b * NCHUNK + c) * Ddim + d;
        carry[o] = h;
        h = fmaf(Aagg[o], h, Xagg[o]);
    }
}

__global__ void scan_p3(const float* __restrict__ a, const float* __restrict__ x,
                        const float* __restrict__ carry,
                        const float* __restrict__ out_in,
                        float* __restrict__ f, float* __restrict__ out_out) {
    int d = blockIdx.x * blockDim.x + threadIdx.x;
    int c = blockIdx.y, b = blockIdx.z;
    size_t base = ((size_t)b * Ldim + (size_t)c * CLEN) * Ddim + d;
    size_t o = ((size_t)b * NCHUNK + c) * Ddim + d;
    float h = carry[o];
#pragma unroll 8
    for (int t = 0; t < CLEN; t++) {
        size_t i = base + (size_t)t * Ddim;
        h = fmaf(a[i], h, x[i]);
        f[i] = h;
        out_out[i] = out_in[i] + h;
    }
}

// ---------------- launch ------------------------------------------------------
extern "C" void kernel_launch(void* const* d_in, const int* in_sizes, int n_in,
                              void* d_out, int out_size) {
    const float* v       = (const float*)d_in[0];
    const float* ctx     = (const float*)d_in[1];
    const float* outp    = (const float*)d_in[2];
    const float* al      = (const float*)d_in[3];
    const float* gr      = (const float*)d_in[4];
    const float* W_alpha = (const float*)d_in[5];
    const float* b_alpha = (const float*)d_in[6];
    const float* W_beta  = (const float*)d_in[7];
    const float* b_beta  = (const float*)d_in[8];
    const float* W_ctx   = (const float*)d_in[9];
    const float* b_ctx   = (const float*)d_in[10];

    float* o_v   = (float*)d_out;
    float* o_ctx = o_v + BLD;
    float* o_out = o_ctx + BLD;
    float* o_al  = o_out + BLD;

    float *p_norm, *p_a, *p_x, *p_f, *p_X, *p_A, *p_c;
    cudaGetSymbolAddress((void**)&p_norm, g_norm);
    cudaGetSymbolAddress((void**)&p_a, g_alpha);
    cudaGetSymbolAddress((void**)&p_x, g_x);
    cudaGetSymbolAddress((void**)&p_f, g_f);
    cudaGetSymbolAddress((void**)&p_X, g_Xagg);
    cudaGetSymbolAddress((void**)&p_A, g_Aagg);
    cudaGetSymbolAddress((void**)&p_c, g_carry);

    // pure pass-through outputs
    cudaMemcpyAsync(o_v, v, BLD * sizeof(float), cudaMemcpyDeviceToDevice, 0);
    cudaMemcpyAsync(o_al, al, BLD * sizeof(float), cudaMemcpyDeviceToDevice, 0);

    // 1) ctx_norm
    rms_kernel<<<Mrows, 256>>>(ctx, gr, p_norm);

    dim3 ggrid(Ddim / BN, Mrows / BM);
    // 2) alpha logits (raw)
    gemm_tf32_kernel<<<ggrid, 256>>>(p_norm, W_alpha, p_a, Mrows, Ddim, Ddim, 0,
                                     nullptr, nullptr, nullptr, nullptr);
    // 3) beta GEMM + fused gate epilogue -> alphas (in p_a), x (in p_x)
    gemm_tf32_kernel<<<ggrid, 256>>>(p_norm, W_beta, p_x, Mrows, Ddim, Ddim, 2,
                                     b_beta, b_alpha, p_a, v);

    // 4) linear recurrence over L
    dim3 sgrid(Ddim / 256, NCHUNK, Bdim);
    scan_p1<<<sgrid, 256>>>(p_a, p_x, p_X, p_A);
    scan_p2<<<(Bdim * Ddim) / 256, 256>>>(p_X, p_A, p_c);
    scan_p3<<<sgrid, 256>>>(p_a, p_x, p_c, outp, p_f, o_out);

    // 5) ctx residual GEMM (fused bias+silu+add)
    gemm_tf32_kernel<<<ggrid, 256>>>(p_f, W_ctx, o_ctx, Mrows, Ddim, Ddim, 1,
                                     b_ctx, nullptr, nullptr, ctx);
}

// round 3
// speedup vs baseline: 1.0656x; 1.0656x over previous
#include <cuda_runtime.h>
#include <cstdint>

// Problem shape (fixed by the dataset)
#define Bdim 4
#define Ldim 4096
#define Ddim 1024
#define Mrows (Bdim * Ldim)          // 16384
#define BLD ((size_t)Bdim * Ldim * Ddim)
#define NCHUNK 64
#define CLEN (Ldim / NCHUNK)         // 64
#define KDIM 1024
#define BKT 32
#define NKT (KDIM / BKT)             // 32
#define TILE_F (128 * 36)            // floats per smem tile (row stride 36)

// ---------------- scratch (static device arrays; no allocation) -------------
__device__ float g_norm[(size_t)Mrows * Ddim];   // ctx_norm (tf32-rounded)
__device__ float g_alpha[(size_t)Mrows * Ddim];  // alphas
__device__ float g_x[(size_t)Mrows * Ddim];      // gated recurrence input x_t
__device__ float g_f[(size_t)Mrows * Ddim];      // fetched (tf32-rounded)
__device__ float g_Xagg[(size_t)Bdim * NCHUNK * Ddim];
__device__ float g_Aagg[(size_t)Bdim * NCHUNK * Ddim];
__device__ float g_carry[(size_t)Bdim * NCHUNK * Ddim];
__device__ float g_Wt[3][(size_t)Ddim * Ddim];   // transposed tf32-rounded weights [N][K]

__device__ __forceinline__ float sigmoidf_(float z) {
    return 1.0f / (1.0f + __expf(-z));
}
__device__ __forceinline__ float tf32r(float f) {
    uint32_t u;
    asm("cvt.rna.tf32.f32 %0, %1;" : "=r"(u) : "f"(f));
    return __uint_as_float(u);
}
__device__ __forceinline__ uint32_t smem_u32(const void* p) {
    return (uint32_t)__cvta_generic_to_shared(p);
}
#define CP16(dst, src) \
    asm volatile("cp.async.cg.shared.global [%0], [%1], 16;\n" ::"r"(dst), "l"(src))

// ---------------- rmsnorm (tf32-rounded output) ------------------------------
__global__ void rms_kernel(const float* __restrict__ ctx,
                           const float* __restrict__ g,
                           float* __restrict__ o) {
    int row = blockIdx.x, tid = threadIdx.x;
    const float4* src = (const float4*)(ctx + (size_t)row * Ddim);
    float4 xv = src[tid];
    float ss = xv.x * xv.x + xv.y * xv.y + xv.z * xv.z + xv.w * xv.w;
#pragma unroll
    for (int off = 16; off > 0; off >>= 1)
        ss += __shfl_xor_sync(0xffffffffu, ss, off);
    __shared__ float ws[8];
    if ((tid & 31) == 0) ws[tid >> 5] = ss;
    __syncthreads();
    float tot = ws[0] + ws[1] + ws[2] + ws[3] + ws[4] + ws[5] + ws[6] + ws[7];
    float r = rsqrtf(tot * (1.0f / Ddim) + 1e-6f);
    float4 gv = ((const float4*)g)[tid];
    float4 ov = make_float4(tf32r(xv.x * r * gv.x), tf32r(xv.y * r * gv.y),
                            tf32r(xv.z * r * gv.z), tf32r(xv.w * r * gv.w));
    ((float4*)(o + (size_t)row * Ddim))[tid] = ov;
}

// ---------------- weight transpose ([K,N] -> [N,K], tf32-rounded) ------------
__global__ void transpose_kernel(const float* __restrict__ W, float* __restrict__ Wt) {
    __shared__ float tile[32][33];
    int x = blockIdx.x * 32 + threadIdx.x;
    int y = blockIdx.y * 32 + threadIdx.y;
#pragma unroll
    for (int j = 0; j < 32; j += 8)
        tile[threadIdx.y + j][threadIdx.x] = W[(size_t)(y + j) * Ddim + x];
    __syncthreads();
    int nx = blockIdx.y * 32 + threadIdx.x;
    int ny = blockIdx.x * 32 + threadIdx.y;
#pragma unroll
    for (int j = 0; j < 32; j += 8)
        Wt[(size_t)(ny + j) * Ddim + nx] = tf32r(tile[threadIdx.x][threadIdx.y + j]);
}

// ================= TF32 mma.sync GEMM (conflict-free SMEM, 3-stage) ==========
// All SMEM tiles stored K-minor: T[row][k] with row stride 36 floats
// (36 % 32 == 4 -> fragment LDS bank = 4*gid + tig : conflict-free).
// FUSED (512 thr): warpgroup 0 -> C1 = A*W1t, warpgroup 1 -> C2 = A*W2t
//   gate epilogue: a = sigmoid(C1 + b1); beta = silu(C2 + b2);
//                  out1 = a; out2 = aux * beta * sqrt(max(1-a^2,1e-6))
// !FUSED (256 thr): out1 = aux + silu(C1 + b1)
template <bool FUSED>
__global__ void __launch_bounds__(FUSED ? 512 : 256, FUSED ? 1 : 2) gemm_mma(
    const float* __restrict__ A, const float* __restrict__ W1t,
    const float* __restrict__ W2t,
    const float* __restrict__ bias1, const float* __restrict__ bias2,
    const float* __restrict__ aux,
    float* __restrict__ out1, float* __restrict__ out2) {
    constexpr int NT = FUSED ? 512 : 256;
    constexpr int NTILES = FUSED ? 3 : 2;
    constexpr int STAGE_F = NTILES * TILE_F;
    extern __shared__ float smem[];

    const int tid = threadIdx.x;
    const int warp = tid >> 5, lane = tid & 31;
    const int wg = FUSED ? (warp >> 3) : 0;   // warpgroup (0/1)
    const int w8 = warp & 7;
    const int wm = w8 >> 1, wn = w8 & 1;      // 4x2 warp grid over 128x128
    const int gid = lane >> 2, tig = lane & 3;
    const int m0 = blockIdx.y * 128, n0 = blockIdx.x * 128;

    float acc[2][8][4];
#pragma unroll
    for (int i = 0; i < 2; i++)
#pragma unroll
        for (int j = 0; j < 8; j++)
#pragma unroll
            for (int k = 0; k < 4; k++) acc[i][j][k] = 0.0f;

    auto ld_tile = [&](const float* gsrc, float* sdst, int row_off, int k0) {
#pragma unroll
        for (int j = 0; j < 1024 / NT; j++) {
            int i = tid + j * NT;
            int row = i >> 3, c4 = (i & 7) << 2;
            CP16(smem_u32(sdst + row * 36 + c4),
                 gsrc + (size_t)(row_off + row) * KDIM + k0 + c4);
        }
    };
    auto load_stage = [&](int kt, int s) {
        const int k0 = kt * BKT;
        float* sb = smem + s * STAGE_F;
        ld_tile(A, sb, m0, k0);
        ld_tile(W1t, sb + TILE_F, n0, k0);
        if (FUSED) ld_tile(W2t, sb + 2 * TILE_F, n0, k0);
        asm volatile("cp.async.commit_group;\n");
    };

    load_stage(0, 0);
    load_stage(1, 1);

    int s = 0;
    for (int kt = 0; kt < NKT; kt++) {
        if (kt < NKT - 1)
            asm volatile("cp.async.wait_group 1;\n");
        else
            asm volatile("cp.async.wait_group 0;\n");
        __syncthreads();
        if (kt + 2 < NKT) {
            int s2 = s + 2;
            if (s2 >= 3) s2 -= 3;
            load_stage(kt + 2, s2);
        }

        const float* As = smem + s * STAGE_F;
        const float* Bs = smem + s * STAGE_F + (1 + wg) * TILE_F;
#pragma unroll
        for (int ks = 0; ks < 4; ks++) {
            const int ko = ks * 8;
            uint32_t af[2][4], bf[8][2];
#pragma unroll
            for (int mf = 0; mf < 2; mf++) {
                int r = wm * 32 + mf * 16 + gid;
                af[mf][0] = __float_as_uint(As[r * 36 + ko + tig]);
                af[mf][1] = __float_as_uint(As[(r + 8) * 36 + ko + tig]);
                af[mf][2] = __float_as_uint(As[r * 36 + ko + tig + 4]);
                af[mf][3] = __float_as_uint(As[(r + 8) * 36 + ko + tig + 4]);
            }
#pragma unroll
            for (int nf = 0; nf < 8; nf++) {
                int c = wn * 64 + nf * 8 + gid;
                bf[nf][0] = __float_as_uint(Bs[c * 36 + ko + tig]);
                bf[nf][1] = __float_as_uint(Bs[c * 36 + ko + tig + 4]);
            }
#pragma unroll
            for (int mf = 0; mf < 2; mf++)
#pragma unroll
                for (int nf = 0; nf < 8; nf++) {
                    asm volatile(
                        "mma.sync.aligned.m16n8k8.row.col.f32.tf32.tf32.f32 "
                        "{%0,%1,%2,%3}, {%4,%5,%6,%7}, {%8,%9}, {%0,%1,%2,%3};\n"
                        : "+f"(acc[mf][nf][0]), "+f"(acc[mf][nf][1]),
                          "+f"(acc[mf][nf][2]), "+f"(acc[mf][nf][3])
                        : "r"(af[mf][0]), "r"(af[mf][1]), "r"(af[mf][2]),
                          "r"(af[mf][3]), "r"(bf[nf][0]), "r"(bf[nf][1]));
                }
        }
        if (++s == 3) s = 0;
    }

    // ---------------- epilogue ----------------
    if (FUSED) {
        // exchange: wg1 (beta) acc -> smem, wg0 reads and applies the gate
        __syncthreads();
        float* ex = smem;  // 128x132
        if (wg == 1) {
#pragma unroll
            for (int mf = 0; mf < 2; mf++)
#pragma unroll
                for (int nf = 0; nf < 8; nf++) {
                    int row = wm * 32 + mf * 16 + gid;
                    int col = wn * 64 + nf * 8 + tig * 2;
#pragma unroll
                    for (int h = 0; h < 2; h++) {
                        ex[(row + h * 8) * 132 + col] = acc[mf][nf][h * 2];
                        ex[(row + h * 8) * 132 + col + 1] = acc[mf][nf][h * 2 + 1];
                    }
                }
        }
        __syncthreads();
        if (wg == 0) {
#pragma unroll
            for (int mf = 0; mf < 2; mf++)
#pragma unroll
                for (int nf = 0; nf < 8; nf++) {
                    int rowl = wm * 32 + mf * 16 + gid;
                    int col = wn * 64 + nf * 8 + tig * 2;
#pragma unroll
                    for (int h = 0; h < 2; h++) {
                        int rl = rowl + h * 8;
                        size_t idx = (size_t)(m0 + rl) * Ddim + n0 + col;
                        float a0 = sigmoidf_(acc[mf][nf][h * 2] + bias1[n0 + col]);
                        float a1 = sigmoidf_(acc[mf][nf][h * 2 + 1] + bias1[n0 + col + 1]);
                        float zb0 = ex[rl * 132 + col] + bias2[n0 + col];
                        float zb1 = ex[rl * 132 + col + 1] + bias2[n0 + col + 1];
                        float be0 = zb0 * sigmoidf_(zb0);
                        float be1 = zb1 * sigmoidf_(zb1);
                        float w0 = sqrtf(fmaxf(1.0f - a0 * a0, 1e-6f));
                        float w1 = sqrtf(fmaxf(1.0f - a1 * a1, 1e-6f));
                        float2 vv = *(const float2*)(aux + idx);
                        *(float2*)(out1 + idx) = make_float2(a0, a1);
                        *(float2*)(out2 + idx) =
                            make_float2(vv.x * be0 * w0, vv.y * be1 * w1);
                    }
                }
        }
    } else {
#pragma unroll
        for (int mf = 0; mf < 2; mf++)
#pragma unroll
            for (int nf = 0; nf < 8; nf++) {
                int rowl = wm * 32 + mf * 16 + gid;
                int col = wn * 64 + nf * 8 + tig * 2;
#pragma unroll
                for (int h = 0; h < 2; h++) {
                    int rl = rowl + h * 8;
                    size_t idx = (size_t)(m0 + rl) * Ddim + n0 + col;
                    float z0 = acc[mf][nf][h * 2] + bias1[n0 + col];
                    float z1 = acc[mf][nf][h * 2 + 1] + bias1[n0 + col + 1];
                    float2 cv = *(const float2*)(aux + idx);
                    *(float2*)(out1 + idx) = make_float2(
                        cv.x + z0 * sigmoidf_(z0), cv.y + z1 * sigmoidf_(z1));
                }
            }
    }
}

// ---------------- chunked linear recurrence (h_t = a_t h_{t-1} + x_t) --------
__global__ void scan_p1(const float* __restrict__ a, const float* __restrict__ x,
                        float* __restrict__ Xagg, float* __restrict__ Aagg) {
    int d = blockIdx.x * blockDim.x + threadIdx.x;
    int c = blockIdx.y, b = blockIdx.z;
    size_t base = ((size_t)b * Ldim + (size_t)c * CLEN) * Ddim + d;
    float X = 0.0f, A = 1.0f;
#pragma unroll 8
    for (int t = 0; t < CLEN; t++) {
        float at = a[base + (size_t)t * Ddim];
        float xt = x[base + (size_t)t * Ddim];
        X = fmaf(at, X, xt);
        A *= at;
    }
    size_t o = ((size_t)b * NCHUNK + c) * Ddim + d;
    Xagg[o] = X;
    Aagg[o] = A;
}

__global__ void scan_p2(const float* __restrict__ Xagg,
                        const float* __restrict__ Aagg,
                        float* __restrict__ carry) {
    int i = blockIdx.x * blockDim.x + threadIdx.x;
    int b = i / Ddim, d = i % Ddim;
    float h = 0.0f;
#pragma unroll 8
    for (int c = 0; c < NCHUNK; c++) {
        size_t o = ((size_t)b * NCHUNK + c) * Ddim + d;
        carry[o] = h;
        h = fmaf(Aagg[o], h, Xagg[o]);
    }
}

__global__ void scan_p3(const float* __restrict__ a, const float* __restrict__ x,
                        const float* __restrict__ carry,
                        const float* __restrict__ out_in,
                        float* __restrict__ f, float* __restrict__ out_out) {
    int d = blockIdx.x * blockDim.x + threadIdx.x;
    int c = blockIdx.y, b = blockIdx.z;
    size_t base = ((size_t)b * Ldim + (size_t)c * CLEN) * Ddim + d;
    size_t o = ((size_t)b * NCHUNK + c) * Ddim + d;
    float h = carry[o];
#pragma unroll 8
    for (int t = 0; t < CLEN; t++) {
        size_t i = base + (size_t)t * Ddim;
        h = fmaf(a[i], h, x[i]);
        f[i] = tf32r(h);            // GEMM3 input: pre-rounded
        out_out[i] = out_in[i] + h; // exact residual
    }
}

// ---------------- launch ------------------------------------------------------
extern "C" void kernel_launch(void* const* d_in, const int* in_sizes, int n_in,
                              void* d_out, int out_size) {
    const float* v       = (const float*)d_in[0];
    const float* ctx     = (const float*)d_in[1];
    const float* outp    = (const float*)d_in[2];
    const float* al      = (const float*)d_in[3];
    const float* gr      = (const float*)d_in[4];
    const float* W_alpha = (const float*)d_in[5];
    const float* b_alpha = (const float*)d_in[6];
    const float* W_beta  = (const float*)d_in[7];
    const float* b_beta  = (const float*)d_in[8];
    const float* W_ctx   = (const float*)d_in[9];
    const float* b_ctx   = (const float*)d_in[10];

    float* o_v   = (float*)d_out;
    float* o_ctx = o_v + BLD;
    float* o_out = o_ctx + BLD;
    float* o_al  = o_out + BLD;

    float *p_norm, *p_a, *p_x, *p_f, *p_X, *p_A, *p_c, *p_W;
    cudaGetSymbolAddress((void**)&p_norm, g_norm);
    cudaGetSymbolAddress((void**)&p_a, g_alpha);
    cudaGetSymbolAddress((void**)&p_x, g_x);
    cudaGetSymbolAddress((void**)&p_f, g_f);
    cudaGetSymbolAddress((void**)&p_X, g_Xagg);
    cudaGetSymbolAddress((void**)&p_A, g_Aagg);
    cudaGetSymbolAddress((void**)&p_c, g_carry);
    cudaGetSymbolAddress((void**)&p_W, g_Wt);
    float* p_wa = p_W;
    float* p_wb = p_W + (size_t)Ddim * Ddim;
    float* p_wc = p_W + 2 * (size_t)Ddim * Ddim;

    const int SMEMF = 3 * 3 * TILE_F * 4;  // 165888 B
    const int SMEMS = 3 * 2 * TILE_F * 4;  // 110592 B
    cudaFuncSetAttribute(gemm_mma<true>,
                         cudaFuncAttributeMaxDynamicSharedMemorySize, SMEMF);
    cudaFuncSetAttribute(gemm_mma<false>,
                         cudaFuncAttributeMaxDynamicSharedMemorySize, SMEMS);

    // pure pass-through outputs
    cudaMemcpyAsync(o_v, v, BLD * sizeof(float), cudaMemcpyDeviceToDevice, 0);
    cudaMemcpyAsync(o_al, al, BLD * sizeof(float), cudaMemcpyDeviceToDevice, 0);

    // weight transposes (tf32-rounded, [N][K])
    dim3 tgrid(Ddim / 32, Ddim / 32), tblk(32, 8);
    transpose_kernel<<<tgrid, tblk>>>(W_alpha, p_wa);
    transpose_kernel<<<tgrid, tblk>>>(W_beta, p_wb);
    transpose_kernel<<<tgrid, tblk>>>(W_ctx, p_wc);

    // 1) ctx_norm (rounded)
    rms_kernel<<<Mrows, 256>>>(ctx, gr, p_norm);

    // 2) fused alpha+beta GEMM + gate epilogue -> alphas (p_a), x (p_x)
    dim3 ggrid(Ddim / 128, Mrows / 128);  // (8, 128)
    gemm_mma<true><<<ggrid, 512, SMEMF>>>(p_norm, p_wa, p_wb, b_alpha, b_beta,
                                          v, p_a, p_x);

    // 3) linear recurrence over L
    dim3 sgrid(Ddim / 256, NCHUNK, Bdim);
    scan_p1<<<sgrid, 256>>>(p_a, p_x, p_X, p_A);
    scan_p2<<<(Bdim * Ddim) / 256, 256>>>(p_X, p_A, p_c);
    scan_p3<<<sgrid, 256>>>(p_a, p_x, p_c, outp, p_f, o_out);

    // 4) ctx residual GEMM (fused bias+silu+add)
    gemm_mma<false><<<ggrid, 256, SMEMS>>>(p_f, p_wc, nullptr, b_ctx, nullptr,
                                           ctx, o_ctx, nullptr);
}

// round 4
// speedup vs baseline: 1.4545x; 1.3649x over previous
#include <cuda_runtime.h>
#include <cuda_fp16.h>
#include <cstdint>

// Problem shape (fixed by the dataset)
#define Bdim 4
#define Ldim 4096
#define Ddim 1024
#define Mrows (Bdim * Ldim)          // 16384
#define BLD ((size_t)Bdim * Ldim * Ddim)
#define NCHUNK 64
#define CLEN (Ldim / NCHUNK)         // 64
#define KDIM 1024
#define BKT 32
#define NKT (KDIM / BKT)             // 32
#define RS 40                        // smem row stride in halves (bank-conflict-free)
#define TILE_H (128 * RS)            // halves per smem tile

// ---------------- scratch (static device arrays; no allocation) -------------
__device__ __half g_norm[(size_t)Mrows * Ddim];  // ctx_norm (fp16)
__device__ float  g_alpha[(size_t)Mrows * Ddim]; // alphas (fp32 for scan precision)
__device__ float  g_x[(size_t)Mrows * Ddim];     // gated recurrence input x_t
__device__ __half g_f[(size_t)Mrows * Ddim];     // fetched (fp16, GEMM3 input)
__device__ float  g_Xagg[(size_t)Bdim * NCHUNK * Ddim];
__device__ float  g_Aagg[(size_t)Bdim * NCHUNK * Ddim];
__device__ float  g_carry[(size_t)Bdim * NCHUNK * Ddim];
__device__ __half g_Wt[3][(size_t)Ddim * Ddim];  // transposed fp16 weights [N][K]

__device__ __forceinline__ float sigmoidf_(float z) {
    return 1.0f / (1.0f + __expf(-z));
}
__device__ __forceinline__ uint32_t smem_u32(const void* p) {
    return (uint32_t)__cvta_generic_to_shared(p);
}
#define CP16(dst, src) \
    asm volatile("cp.async.cg.shared.global [%0], [%1], 16;\n" ::"r"(dst), "l"(src))

// ---------------- rmsnorm (fp16 output) --------------------------------------
__global__ void rms_kernel(const float* __restrict__ ctx,
                           const float* __restrict__ g,
                           __half* __restrict__ o) {
    int row = blockIdx.x, tid = threadIdx.x;
    const float4* src = (const float4*)(ctx + (size_t)row * Ddim);
    float4 xv = src[tid];
    float ss = xv.x * xv.x + xv.y * xv.y + xv.z * xv.z + xv.w * xv.w;
#pragma unroll
    for (int off = 16; off > 0; off >>= 1)
        ss += __shfl_xor_sync(0xffffffffu, ss, off);
    __shared__ float ws[8];
    if ((tid & 31) == 0) ws[tid >> 5] = ss;
    __syncthreads();
    float tot = ws[0] + ws[1] + ws[2] + ws[3] + ws[4] + ws[5] + ws[6] + ws[7];
    float r = rsqrtf(tot * (1.0f / Ddim) + 1e-6f);
    float4 gv = ((const float4*)g)[tid];
    __half2 h01 = __floats2half2_rn(xv.x * r * gv.x, xv.y * r * gv.y);
    __half2 h23 = __floats2half2_rn(xv.z * r * gv.z, xv.w * r * gv.w);
    __half2* dst = (__half2*)(o + (size_t)row * Ddim);
    dst[tid * 2] = h01;
    dst[tid * 2 + 1] = h23;
}

// ---------------- weight transpose ([K,N] fp32 -> [N,K] fp16) ----------------
__global__ void transpose_kernel(const float* __restrict__ W, __half* __restrict__ Wt) {
    __shared__ float tile[32][33];
    int x = blockIdx.x * 32 + threadIdx.x;
    int y = blockIdx.y * 32 + threadIdx.y;
#pragma unroll
    for (int j = 0; j < 32; j += 8)
        tile[threadIdx.y + j][threadIdx.x] = W[(size_t)(y + j) * Ddim + x];
    __syncthreads();
    int nx = blockIdx.y * 32 + threadIdx.x;
    int ny = blockIdx.x * 32 + threadIdx.y;
#pragma unroll
    for (int j = 0; j < 32; j += 8)
        Wt[(size_t)(ny + j) * Ddim + nx] = __float2half_rn(tile[threadIdx.x][threadIdx.y + j]);
}

// ================= FP16 mma.sync GEMM (m16n8k16, 4-stage cp.async) ===========
// SMEM tiles K-minor: T[row][k], row stride RS=40 halves.
//   fragment LDS.32 bank = (20*gid + tig) mod 32 -> conflict-free.
// FUSED (512 thr): warpgroup 0 -> C1 = A*W1t, warpgroup 1 -> C2 = A*W2t
//   gate epilogue: a = sigmoid(C1+b1); beta = silu(C2+b2);
//                  out1 = a; out2 = aux * beta * sqrt(max(1-a^2,1e-6))
// !FUSED (256 thr): out1 = aux + silu(C1 + b1)
template <bool FUSED>
__global__ void __launch_bounds__(FUSED ? 512 : 256, FUSED ? 1 : 2) gemm_mma(
    const __half* __restrict__ A, const __half* __restrict__ W1t,
    const __half* __restrict__ W2t,
    const float* __restrict__ bias1, const float* __restrict__ bias2,
    const float* __restrict__ aux,
    float* __restrict__ out1, float* __restrict__ out2) {
    constexpr int NT = FUSED ? 512 : 256;
    constexpr int NTILES = FUSED ? 3 : 2;
    constexpr int STAGE_H = NTILES * TILE_H;
    extern __shared__ __half smh[];

    const int tid = threadIdx.x;
    const int warp = tid >> 5, lane = tid & 31;
    const int wg = FUSED ? (warp >> 3) : 0;   // warpgroup (0/1)
    const int w8 = warp & 7;
    const int wm = w8 >> 1, wn = w8 & 1;      // 4x2 warp grid over 128x128
    const int gid = lane >> 2, tig = lane & 3;
    const int m0 = blockIdx.y * 128, n0 = blockIdx.x * 128;

    float acc[2][8][4];
#pragma unroll
    for (int i = 0; i < 2; i++)
#pragma unroll
        for (int j = 0; j < 8; j++)
#pragma unroll
            for (int k = 0; k < 4; k++) acc[i][j][k] = 0.0f;

    // 512 16B-chunks per tile (128 rows x 4 chunks of 8 halves)
    auto ld_tile = [&](const __half* gsrc, __half* sdst, int row_off, int k0) {
#pragma unroll
        for (int j = 0; j < 512 / NT; j++) {
            int i = tid + j * NT;
            int row = i >> 2, c = i & 3;
            CP16(smem_u32(sdst + row * RS + c * 8),
                 gsrc + (size_t)(row_off + row) * KDIM + k0 + c * 8);
        }
    };
    auto load_stage = [&](int kt, int s) {
        const int k0 = kt * BKT;
        __half* sb = smh + s * STAGE_H;
        ld_tile(A, sb, m0, k0);
        ld_tile(W1t, sb + TILE_H, n0, k0);
        if (FUSED) ld_tile(W2t, sb + 2 * TILE_H, n0, k0);
        asm volatile("cp.async.commit_group;\n");
    };

    load_stage(0, 0);
    load_stage(1, 1);
    load_stage(2, 2);

    int s = 0;
    for (int kt = 0; kt < NKT; kt++) {
        if (kt >= NKT - 2)
            asm volatile("cp.async.wait_group 0;\n");
        else
            asm volatile("cp.async.wait_group 2;\n");
        __syncthreads();
        if (kt + 3 < NKT) load_stage(kt + 3, (s + 3) & 3);

        const __half* As = smh + s * STAGE_H;
        const __half* Bs = As + (1 + wg) * TILE_H;
#pragma unroll
        for (int ks = 0; ks < 2; ks++) {
            const int ko = ks * 16;
            uint32_t af[2][4], bf[8][2];
#pragma unroll
            for (int mf = 0; mf < 2; mf++) {
                int r = wm * 32 + mf * 16 + gid;
                af[mf][0] = *(const uint32_t*)&As[r * RS + ko + 2 * tig];
                af[mf][1] = *(const uint32_t*)&As[(r + 8) * RS + ko + 2 * tig];
                af[mf][2] = *(const uint32_t*)&As[r * RS + ko + 2 * tig + 8];
                af[mf][3] = *(const uint32_t*)&As[(r + 8) * RS + ko + 2 * tig + 8];
            }
#pragma unroll
            for (int nf = 0; nf < 8; nf++) {
                int c = wn * 64 + nf * 8 + gid;
                bf[nf][0] = *(const uint32_t*)&Bs[c * RS + ko + 2 * tig];
                bf[nf][1] = *(const uint32_t*)&Bs[c * RS + ko + 2 * tig + 8];
            }
#pragma unroll
            for (int mf = 0; mf < 2; mf++)
#pragma unroll
                for (int nf = 0; nf < 8; nf++) {
                    asm volatile(
                        "mma.sync.aligned.m16n8k16.row.col.f32.f16.f16.f32 "
                        "{%0,%1,%2,%3}, {%4,%5,%6,%7}, {%8,%9}, {%0,%1,%2,%3};\n"
                        : "+f"(acc[mf][nf][0]), "+f"(acc[mf][nf][1]),
                          "+f"(acc[mf][nf][2]), "+f"(acc[mf][nf][3])
                        : "r"(af[mf][0]), "r"(af[mf][1]), "r"(af[mf][2]),
                          "r"(af[mf][3]), "r"(bf[nf][0]), "r"(bf[nf][1]));
                }
        }
        s = (s + 1) & 3;
    }

    // ---------------- epilogue ----------------
    if (FUSED) {
        // exchange: wg1 (beta) acc -> smem, wg0 reads and applies the gate
        __syncthreads();
        float* ex = (float*)smh;  // 128x132 fp32
        if (wg == 1) {
#pragma unroll
            for (int mf = 0; mf < 2; mf++)
#pragma unroll
                for (int nf = 0; nf < 8; nf++) {
                    int row = wm * 32 + mf * 16 + gid;
                    int col = wn * 64 + nf * 8 + tig * 2;
#pragma unroll
                    for (int h = 0; h < 2; h++) {
                        ex[(row + h * 8) * 132 + col] = acc[mf][nf][h * 2];
                        ex[(row + h * 8) * 132 + col + 1] = acc[mf][nf][h * 2 + 1];
                    }
                }
        }
        __syncthreads();
        if (wg == 0) {
#pragma unroll
            for (int mf = 0; mf < 2; mf++)
#pragma unroll
                for (int nf = 0; nf < 8; nf++) {
                    int rowl = wm * 32 + mf * 16 + gid;
                    int col = wn * 64 + nf * 8 + tig * 2;
#pragma unroll
                    for (int h = 0; h < 2; h++) {
                        int rl = rowl + h * 8;
                        size_t idx = (size_t)(m0 + rl) * Ddim + n0 + col;
                        float a0 = sigmoidf_(acc[mf][nf][h * 2] + bias1[n0 + col]);
                        float a1 = sigmoidf_(acc[mf][nf][h * 2 + 1] + bias1[n0 + col + 1]);
                        float zb0 = ex[rl * 132 + col] + bias2[n0 + col];
                        float zb1 = ex[rl * 132 + col + 1] + bias2[n0 + col + 1];
                        float be0 = zb0 * sigmoidf_(zb0);
                        float be1 = zb1 * sigmoidf_(zb1);
                        float w0 = sqrtf(fmaxf(1.0f - a0 * a0, 1e-6f));
                        float w1 = sqrtf(fmaxf(1.0f - a1 * a1, 1e-6f));
                        float2 vv = *(const float2*)(aux + idx);
                        *(float2*)(out1 + idx) = make_float2(a0, a1);
                        *(float2*)(out2 + idx) =
                            make_float2(vv.x * be0 * w0, vv.y * be1 * w1);
                    }
                }
        }
    } else {
#pragma unroll
        for (int mf = 0; mf < 2; mf++)
#pragma unroll
            for (int nf = 0; nf < 8; nf++) {
                int rowl = wm * 32 + mf * 16 + gid;
                int col = wn * 64 + nf * 8 + tig * 2;
#pragma unroll
                for (int h = 0; h < 2; h++) {
                    int rl = rowl + h * 8;
                    size_t idx = (size_t)(m0 + rl) * Ddim + n0 + col;
                    float z0 = acc[mf][nf][h * 2] + bias1[n0 + col];
                    float z1 = acc[mf][nf][h * 2 + 1] + bias1[n0 + col + 1];
                    float2 cv = *(const float2*)(aux + idx);
                    *(float2*)(out1 + idx) = make_float2(
                        cv.x + z0 * sigmoidf_(z0), cv.y + z1 * sigmoidf_(z1));
                }
            }
    }
}

// ---------------- chunked linear recurrence (h_t = a_t h_{t-1} + x_t) --------
__global__ void scan_p1(const float* __restrict__ a, const float* __restrict__ x,
                        float* __restrict__ Xagg, float* __restrict__ Aagg) {
    int d = blockIdx.x * blockDim.x + threadIdx.x;
    int c = blockIdx.y, b = blockIdx.z;
    size_t base = ((size_t)b * Ldim + (size_t)c * CLEN) * Ddim + d;
    float X = 0.0f, A = 1.0f;
#pragma unroll 8
    for (int t = 0; t < CLEN; t++) {
        float at = a[base + (size_t)t * Ddim];
        float xt = x[base + (size_t)t * Ddim];
        X = fmaf(at, X, xt);
        A *= at;
    }
    size_t o = ((size_t)b * NCHUNK + c) * Ddim + d;
    Xagg[o] = X;
    Aagg[o] = A;
}

__global__ void scan_p2(const float* __restrict__ Xagg,
                        const float* __restrict__ Aagg,
                        float* __restrict__ carry) {
    int i = blockIdx.x * blockDim.x + threadIdx.x;
    int b = i / Ddim, d = i % Ddim;
    float h = 0.0f;
#pragma unroll 8
    for (int c = 0; c < NCHUNK; c++) {
        size_t o = ((size_t)b * NCHUNK + c) * Ddim + d;
        carry[o] = h;
        h = fmaf(Aagg[o], h, Xagg[o]);
    }
}

__global__ void scan_p3(const float* __restrict__ a, const float* __restrict__ x,
                        const float* __restrict__ carry,
                        const float* __restrict__ out_in,
                        __half* __restrict__ f, float* __restrict__ out_out) {
    int d = blockIdx.x * blockDim.x + threadIdx.x;
    int c = blockIdx.y, b = blockIdx.z;
    size_t base = ((size_t)b * Ldim + (size_t)c * CLEN) * Ddim + d;
    size_t o = ((size_t)b * NCHUNK + c) * Ddim + d;
    float h = carry[o];
#pragma unroll 8
    for (int t = 0; t < CLEN; t++) {
        size_t i = base + (size_t)t * Ddim;
        h = fmaf(a[i], h, x[i]);
        f[i] = __float2half_rn(h);  // GEMM3 input (fp16)
        out_out[i] = out_in[i] + h; // exact residual
    }
}

// ---------------- launch ------------------------------------------------------
extern "C" void kernel_launch(void* const* d_in, const int* in_sizes, int n_in,
                              void* d_out, int out_size) {
    const float* v       = (const float*)d_in[0];
    const float* ctx     = (const float*)d_in[1];
    const float* outp    = (const float*)d_in[2];
    const float* al      = (const float*)d_in[3];
    const float* gr      = (const float*)d_in[4];
    const float* W_alpha = (const float*)d_in[5];
    const float* b_alpha = (const float*)d_in[6];
    const float* W_beta  = (const float*)d_in[7];
    const float* b_beta  = (const float*)d_in[8];
    const float* W_ctx   = (const float*)d_in[9];
    const float* b_ctx   = (const float*)d_in[10];

    float* o_v   = (float*)d_out;
    float* o_ctx = o_v + BLD;
    float* o_out = o_ctx + BLD;
    float* o_al  = o_out + BLD;

    __half *p_norm, *p_f, *p_W;
    float *p_a, *p_x, *p_X, *p_A, *p_c;
    cudaGetSymbolAddress((void**)&p_norm, g_norm);
    cudaGetSymbolAddress((void**)&p_a, g_alpha);
    cudaGetSymbolAddress((void**)&p_x, g_x);
    cudaGetSymbolAddress((void**)&p_f, g_f);
    cudaGetSymbolAddress((void**)&p_X, g_Xagg);
    cudaGetSymbolAddress((void**)&p_A, g_Aagg);
    cudaGetSymbolAddress((void**)&p_c, g_carry);
    cudaGetSymbolAddress((void**)&p_W, g_Wt);
    __half* p_wa = p_W;
    __half* p_wb = p_W + (size_t)Ddim * Ddim;
    __half* p_wc = p_W + 2 * (size_t)Ddim * Ddim;

    const int SMEMF = 4 * 3 * TILE_H * 2;  // 122880 B
    const int SMEMS = 4 * 2 * TILE_H * 2;  // 81920 B
    cudaFuncSetAttribute(gemm_mma<true>,
                         cudaFuncAttributeMaxDynamicSharedMemorySize, SMEMF);
    cudaFuncSetAttribute(gemm_mma<false>,
                         cudaFuncAttributeMaxDynamicSharedMemorySize, SMEMS);

    // pure pass-through outputs
    cudaMemcpyAsync(o_v, v, BLD * sizeof(float), cudaMemcpyDeviceToDevice, 0);
    cudaMemcpyAsync(o_al, al, BLD * sizeof(float), cudaMemcpyDeviceToDevice, 0);

    // weight transposes (fp16, [N][K])
    dim3 tgrid(Ddim / 32, Ddim / 32), tblk(32, 8);
    transpose_kernel<<<tgrid, tblk>>>(W_alpha, p_wa);
    transpose_kernel<<<tgrid, tblk>>>(W_beta, p_wb);
    transpose_kernel<<<tgrid, tblk>>>(W_ctx, p_wc);

    // 1) ctx_norm (fp16)
    rms_kernel<<<Mrows, 256>>>(ctx, gr, p_norm);

    // 2) fused alpha+beta GEMM + gate epilogue -> alphas (p_a), x (p_x)
    dim3 ggrid(Ddim / 128, Mrows / 128);  // (8, 128)
    gemm_mma<true><<<ggrid, 512, SMEMF>>>(p_norm, p_wa, p_wb, b_alpha, b_beta,
                                          v, p_a, p_x);

    // 3) linear recurrence over L
    dim3 sgrid(Ddim / 256, NCHUNK, Bdim);
    scan_p1<<<sgrid, 256>>>(p_a, p_x, p_X, p_A);
    scan_p2<<<(Bdim * Ddim) / 256, 256>>>(p_X, p_A, p_c);
    scan_p3<<<sgrid, 256>>>(p_a, p_x, p_c, outp, p_f, o_out);

    // 4) ctx residual GEMM (fused bias+silu+add)
    gemm_mma<false><<<ggrid, 256, SMEMS>>>(p_f, p_wc, nullptr, b_ctx, nullptr,
                                           ctx, o_ctx, nullptr);
}

// round 6
// speedup vs baseline: 1.5217x; 1.0462x over previous
#include <cuda_runtime.h>
#include <cuda_fp16.h>
#include <cstdint>

// Problem shape (fixed by the dataset)
#define Bdim 4
#define Ldim 4096
#define Ddim 1024
#define Mrows (Bdim * Ldim)          // 16384
#define BLD ((size_t)Bdim * Ldim * Ddim)
#define NCHUNK 64
#define CLEN (Ldim / NCHUNK)         // 64
#define KDIM 1024
#define BKT 32
#define NKT (KDIM / BKT)             // 32
#define RS 40                        // smem row stride in halves (LDSM conflict-free)
#define TILE_H (128 * RS)            // halves per smem tile

// ---------------- scratch (static device arrays; no allocation) -------------
__device__ __half g_norm[(size_t)Mrows * Ddim];  // ctx_norm (fp16)
__device__ float  g_alpha[(size_t)Mrows * Ddim]; // alphas (fp32 for scan precision)
__device__ float  g_x[(size_t)Mrows * Ddim];     // gated recurrence input x_t
__device__ __half g_f[(size_t)Mrows * Ddim];     // fetched (fp16, GEMM3 input)
__device__ float  g_Xagg[(size_t)Bdim * NCHUNK * Ddim];
__device__ float  g_Aagg[(size_t)Bdim * NCHUNK * Ddim];
__device__ float  g_carry[(size_t)Bdim * NCHUNK * Ddim];
__device__ __half g_Wt[3][(size_t)Ddim * Ddim];  // transposed fp16 weights [N][K]

__device__ __forceinline__ float sigmoidf_(float z) {
    return 1.0f / (1.0f + __expf(-z));
}
__device__ __forceinline__ uint32_t smem_u32(const void* p) {
    return (uint32_t)__cvta_generic_to_shared(p);
}
#define CP16(dst, src) \
    asm volatile("cp.async.cg.shared.global [%0], [%1], 16;\n" ::"r"(dst), "l"(src))
#define LDSM4(r0, r1, r2, r3, a)                                             \
    asm volatile("ldmatrix.sync.aligned.m8n8.x4.shared.b16 {%0,%1,%2,%3}, [%4];" \
                 : "=r"(r0), "=r"(r1), "=r"(r2), "=r"(r3) : "r"(a))

// ---------------- rmsnorm (fp16 output) --------------------------------------
__global__ void rms_kernel(const float* __restrict__ ctx,
                           const float* __restrict__ g,
                           __half* __restrict__ o) {
    int row = blockIdx.x, tid = threadIdx.x;
    const float4* src = (const float4*)(ctx + (size_t)row * Ddim);
    float4 xv = src[tid];
    float ss = xv.x * xv.x + xv.y * xv.y + xv.z * xv.z + xv.w * xv.w;
#pragma unroll
    for (int off = 16; off > 0; off >>= 1)
        ss += __shfl_xor_sync(0xffffffffu, ss, off);
    __shared__ float ws[8];
    if ((tid & 31) == 0) ws[tid >> 5] = ss;
    __syncthreads();
    float tot = ws[0] + ws[1] + ws[2] + ws[3] + ws[4] + ws[5] + ws[6] + ws[7];
    float r = rsqrtf(tot * (1.0f / Ddim) + 1e-6f);
    float4 gv = ((const float4*)g)[tid];
    __half2 h01 = __floats2half2_rn(xv.x * r * gv.x, xv.y * r * gv.y);
    __half2 h23 = __floats2half2_rn(xv.z * r * gv.z, xv.w * r * gv.w);
    __half2* dst = (__half2*)(o + (size_t)row * Ddim);
    dst[tid * 2] = h01;
    dst[tid * 2 + 1] = h23;
}

// ---------------- weight transpose ([K,N] fp32 -> [N,K] fp16) ----------------
__global__ void transpose_kernel(const float* __restrict__ W, __half* __restrict__ Wt) {
    __shared__ float tile[32][33];
    int x = blockIdx.x * 32 + threadIdx.x;
    int y = blockIdx.y * 32 + threadIdx.y;
#pragma unroll
    for (int j = 0; j < 32; j += 8)
        tile[threadIdx.y + j][threadIdx.x] = W[(size_t)(y + j) * Ddim + x];
    __syncthreads();
    int nx = blockIdx.y * 32 + threadIdx.x;
    int ny = blockIdx.x * 32 + threadIdx.y;
#pragma unroll
    for (int j = 0; j < 32; j += 8)
        Wt[(size_t)(ny + j) * Ddim + nx] = __float2half_rn(tile[threadIdx.x][threadIdx.y + j]);
}

// ================= FP16 mma.sync GEMM (m16n8k16, ldmatrix, 4-stage) ==========
// SMEM tiles K-minor: T[row][k], row stride RS=40 halves (80 B).
// B stored [n][k] == col-major B -> NON-trans ldmatrix gives the B fragment.
// FUSED (512 thr): warpgroup 0 -> C1 = A*W1t, warpgroup 1 -> C2 = A*W2t
//   gate epilogue: a = sigmoid(C1+b1); beta = silu(C2+b2);
//                  out1 = a; out2 = aux * beta * sqrt(max(1-a^2,1e-6))
// !FUSED (256 thr): out1 = aux + silu(C1 + b1)
template <bool FUSED>
__global__ void __launch_bounds__(FUSED ? 512 : 256, FUSED ? 1 : 2) gemm_mma(
    const __half* __restrict__ A, const __half* __restrict__ W1t,
    const __half* __restrict__ W2t,
    const float* __restrict__ bias1, const float* __restrict__ bias2,
    const float* __restrict__ aux,
    float* __restrict__ out1, float* __restrict__ out2) {
    constexpr int NT = FUSED ? 512 : 256;
    constexpr int NTILES = FUSED ? 3 : 2;
    constexpr int STAGE_H = NTILES * TILE_H;
    extern __shared__ __half smh[];

    const int tid = threadIdx.x;
    const int warp = tid >> 5, lane = tid & 31;
    const int wg = FUSED ? (warp >> 3) : 0;   // warpgroup (0/1)
    const int w8 = warp & 7;
    const int wm = w8 >> 1, wn = w8 & 1;      // 4x2 warp grid over 128x128
    const int gid = lane >> 2, tig = lane & 3;
    const int m0 = blockIdx.y * 128, n0 = blockIdx.x * 128;

    float acc[2][8][4];
#pragma unroll
    for (int i = 0; i < 2; i++)
#pragma unroll
        for (int j = 0; j < 8; j++)
#pragma unroll
            for (int k = 0; k < 4; k++) acc[i][j][k] = 0.0f;

    // ---- ldmatrix lane-address offsets (halves, relative to tile, excl. ko)
    const int lq = lane >> 3, lr = lane & 7;
    uint32_t a_loff[2], b_loff[4];
#pragma unroll
    for (int mf = 0; mf < 2; mf++)  // A: mats (m0-7,k0-7),(m8-15,k0-7),(m0-7,k8-15),(m8-15,k8-15)
        a_loff[mf] = (uint32_t)((wm * 32 + mf * 16 + lr + (lq & 1) * 8) * RS +
                                (lq >> 1) * 8);
#pragma unroll
    for (int p = 0; p < 4; p++)     // B: mats (n0-7,k0-7),(n0-7,k8-15),(n8-15,k0-7),(n8-15,k8-15)
        b_loff[p] = (uint32_t)((wn * 64 + p * 16 + lr + (lq >> 1) * 8) * RS +
                               (lq & 1) * 8);

    // 512 16B-chunks per tile (128 rows x 4 chunks of 8 halves)
    auto ld_tile = [&](const __half* gsrc, __half* sdst, int row_off, int k0) {
#pragma unroll
        for (int j = 0; j < 512 / NT; j++) {
            int i = tid + j * NT;
            int row = i >> 2, c = i & 3;
            CP16(smem_u32(sdst + row * RS + c * 8),
                 gsrc + (size_t)(row_off + row) * KDIM + k0 + c * 8);
        }
    };
    auto load_stage = [&](int kt, int s) {
        const int k0 = kt * BKT;
        __half* sb = smh + s * STAGE_H;
        ld_tile(A, sb, m0, k0);
        ld_tile(W1t, sb + TILE_H, n0, k0);
        if (FUSED) ld_tile(W2t, sb + 2 * TILE_H, n0, k0);
        asm volatile("cp.async.commit_group;\n");
    };

    load_stage(0, 0);
    load_stage(1, 1);
    load_stage(2, 2);

    const uint32_t smbase = smem_u32(smh);
    int s = 0;
    for (int kt = 0; kt < NKT; kt++) {
        if (kt >= NKT - 2)
            asm volatile("cp.async.wait_group 0;\n");
        else
            asm volatile("cp.async.wait_group 2;\n");
        __syncthreads();
        if (kt + 3 < NKT) load_stage(kt + 3, (s + 3) & 3);

        const uint32_t a_base = smbase + s * (STAGE_H * 2);
        const uint32_t b_base = a_base + (1 + wg) * (TILE_H * 2);
#pragma unroll
        for (int ks = 0; ks < 2; ks++) {
            const int ko2 = ks * 32;  // ko in bytes (16 halves)
            uint32_t af[2][4], bf[8][2];
#pragma unroll
            for (int mf = 0; mf < 2; mf++)
                LDSM4(af[mf][0], af[mf][1], af[mf][2], af[mf][3],
                      a_base + a_loff[mf] * 2 + ko2);
#pragma unroll
            for (int p = 0; p < 4; p++)
                LDSM4(bf[2 * p][0], bf[2 * p][1], bf[2 * p + 1][0],
                      bf[2 * p + 1][1], b_base + b_loff[p] * 2 + ko2);
#pragma unroll
            for (int mf = 0; mf < 2; mf++)
#pragma unroll
                for (int nf = 0; nf < 8; nf++) {
                    asm volatile(
                        "mma.sync.aligned.m16n8k16.row.col.f32.f16.f16.f32 "
                        "{%0,%1,%2,%3}, {%4,%5,%6,%7}, {%8,%9}, {%0,%1,%2,%3};\n"
                        : "+f"(acc[mf][nf][0]), "+f"(acc[mf][nf][1]),
                          "+f"(acc[mf][nf][2]), "+f"(acc[mf][nf][3])
                        : "r"(af[mf][0]), "r"(af[mf][1]), "r"(af[mf][2]),
                          "r"(af[mf][3]), "r"(bf[nf][0]), "r"(bf[nf][1]));
                }
        }
        s = (s + 1) & 3;
    }

    // ---------------- epilogue ----------------
    if (FUSED) {
        // exchange: wg1 (beta) acc -> smem, wg0 reads and applies the gate
        __syncthreads();
        float* ex = (float*)smh;  // 128x132 fp32
        if (wg == 1) {
#pragma unroll
            for (int mf = 0; mf < 2; mf++)
#pragma unroll
                for (int nf = 0; nf < 8; nf++) {
                    int row = wm * 32 + mf * 16 + gid;
                    int col = wn * 64 + nf * 8 + tig * 2;
#pragma unroll
                    for (int h = 0; h < 2; h++) {
                        ex[(row + h * 8) * 132 + col] = acc[mf][nf][h * 2];
                        ex[(row + h * 8) * 132 + col + 1] = acc[mf][nf][h * 2 + 1];
                    }
                }
        }
        __syncthreads();
        if (wg == 0) {
#pragma unroll
            for (int mf = 0; mf < 2; mf++)
#pragma unroll
                for (int nf = 0; nf < 8; nf++) {
                    int rowl = wm * 32 + mf * 16 + gid;
                    int col = wn * 64 + nf * 8 + tig * 2;
#pragma unroll
                    for (int h = 0; h < 2; h++) {
                        int rl = rowl + h * 8;
                        size_t idx = (size_t)(m0 + rl) * Ddim + n0 + col;
                        float a0 = sigmoidf_(acc[mf][nf][h * 2] + bias1[n0 + col]);
                        float a1 = sigmoidf_(acc[mf][nf][h * 2 + 1] + bias1[n0 + col + 1]);
                        float zb0 = ex[rl * 132 + col] + bias2[n0 + col];
                        float zb1 = ex[rl * 132 + col + 1] + bias2[n0 + col + 1];
                        float be0 = zb0 * sigmoidf_(zb0);
                        float be1 = zb1 * sigmoidf_(zb1);
                        float w0 = sqrtf(fmaxf(1.0f - a0 * a0, 1e-6f));
                        float w1 = sqrtf(fmaxf(1.0f - a1 * a1, 1e-6f));
                        float2 vv = *(const float2*)(aux + idx);
                        *(float2*)(out1 + idx) = make_float2(a0, a1);
                        *(float2*)(out2 + idx) =
                            make_float2(vv.x * be0 * w0, vv.y * be1 * w1);
                    }
                }
        }
    } else {
#pragma unroll
        for (int mf = 0; mf < 2; mf++)
#pragma unroll
            for (int nf = 0; nf < 8; nf++) {
                int rowl = wm * 32 + mf * 16 + gid;
                int col = wn * 64 + nf * 8 + tig * 2;
#pragma unroll
                for (int h = 0; h < 2; h++) {
                    int rl = rowl + h * 8;
                    size_t idx = (size_t)(m0 + rl) * Ddim + n0 + col;
                    float z0 = acc[mf][nf][h * 2] + bias1[n0 + col];
                    float z1 = acc[mf][nf][h * 2 + 1] + bias1[n0 + col + 1];
                    float2 cv = *(const float2*)(aux + idx);
                    *(float2*)(out1 + idx) = make_float2(
                        cv.x + z0 * sigmoidf_(z0), cv.y + z1 * sigmoidf_(z1));
                }
            }
    }
}

// ---------------- chunked linear recurrence (h_t = a_t h_{t-1} + x_t) --------
__global__ void scan_p1(const float* __restrict__ a, const float* __restrict__ x,
                        float* __restrict__ Xagg, float* __restrict__ Aagg) {
    int d = blockIdx.x * blockDim.x + threadIdx.x;
    int c = blockIdx.y, b = blockIdx.z;
    size_t base = ((size_t)b * Ldim + (size_t)c * CLEN) * Ddim + d;
    float X = 0.0f, A = 1.0f;
#pragma unroll 8
    for (int t = 0; t < CLEN; t++) {
        float at = a[base + (size_t)t * Ddim];
        float xt = x[base + (size_t)t * Ddim];
        X = fmaf(at, X, xt);
        A *= at;
    }
    size_t o = ((size_t)b * NCHUNK + c) * Ddim + d;
    Xagg[o] = X;
    Aagg[o] = A;
}

__global__ void scan_p2(const float* __restrict__ Xagg,
                        const float* __restrict__ Aagg,
                        float* __restrict__ carry) {
    int i = blockIdx.x * blockDim.x + threadIdx.x;
    int b = i / Ddim, d = i % Ddim;
    float h = 0.0f;
#pragma unroll 8
    for (int c = 0; c < NCHUNK; c++) {
        size_t o = ((size_t)b * NCHUNK + c) * Ddim + d;
        carry[o] = h;
        h = fmaf(Aagg[o], h, Xagg[o]);
    }
}

__global__ void scan_p3(const float* __restrict__ a, const float* __restrict__ x,
                        const float* __restrict__ carry,
                        const float* __restrict__ out_in,
                        __half* __restrict__ f, float* __restrict__ out_out) {
    int d = blockIdx.x * blockDim.x + threadIdx.x;
    int c = blockIdx.y, b = blockIdx.z;
    size_t base = ((size_t)b * Ldim + (size_t)c * CLEN) * Ddim + d;
    size_t o = ((size_t)b * NCHUNK + c) * Ddim + d;
    float h = carry[o];
#pragma unroll 8
    for (int t = 0; t < CLEN; t++) {
        size_t i = base + (size_t)t * Ddim;
        h = fmaf(a[i], h, x[i]);
        f[i] = __float2half_rn(h);  // GEMM3 input (fp16)
        out_out[i] = out_in[i] + h; // exact residual
    }
}

// ---------------- launch ------------------------------------------------------
extern "C" void kernel_launch(void* const* d_in, const int* in_sizes, int n_in,
                              void* d_out, int out_size) {
    const float* v       = (const float*)d_in[0];
    const float* ctx     = (const float*)d_in[1];
    const float* outp    = (const float*)d_in[2];
    const float* al      = (const float*)d_in[3];
    const float* gr      = (const float*)d_in[4];
    const float* W_alpha = (const float*)d_in[5];
    const float* b_alpha = (const float*)d_in[6];
    const float* W_beta  = (const float*)d_in[7];
    const float* b_beta  = (const float*)d_in[8];
    const float* W_ctx   = (const float*)d_in[9];
    const float* b_ctx   = (const float*)d_in[10];

    float* o_v   = (float*)d_out;
    float* o_ctx = o_v + BLD;
    float* o_out = o_ctx + BLD;
    float* o_al  = o_out + BLD;

    __half *p_norm, *p_f, *p_W;
    float *p_a, *p_x, *p_X, *p_A, *p_c;
    cudaGetSymbolAddress((void**)&p_norm, g_norm);
    cudaGetSymbolAddress((void**)&p_a, g_alpha);
    cudaGetSymbolAddress((void**)&p_x, g_x);
    cudaGetSymbolAddress((void**)&p_f, g_f);
    cudaGetSymbolAddress((void**)&p_X, g_Xagg);
    cudaGetSymbolAddress((void**)&p_A, g_Aagg);
    cudaGetSymbolAddress((void**)&p_c, g_carry);
    cudaGetSymbolAddress((void**)&p_W, g_Wt);
    __half* p_wa = p_W;
    __half* p_wb = p_W + (size_t)Ddim * Ddim;
    __half* p_wc = p_W + 2 * (size_t)Ddim * Ddim;

    const int SMEMF = 4 * 3 * TILE_H * 2;  // 122880 B
    const int SMEMS = 4 * 2 * TILE_H * 2;  // 81920 B
    cudaFuncSetAttribute(gemm_mma<true>,
                         cudaFuncAttributeMaxDynamicSharedMemorySize, SMEMF);
    cudaFuncSetAttribute(gemm_mma<false>,
                         cudaFuncAttributeMaxDynamicSharedMemorySize, SMEMS);

    // pure pass-through outputs
    cudaMemcpyAsync(o_v, v, BLD * sizeof(float), cudaMemcpyDeviceToDevice, 0);
    cudaMemcpyAsync(o_al, al, BLD * sizeof(float), cudaMemcpyDeviceToDevice, 0);

    // weight transposes (fp16, [N][K])
    dim3 tgrid(Ddim / 32, Ddim / 32), tblk(32, 8);
    transpose_kernel<<<tgrid, tblk>>>(W_alpha, p_wa);
    transpose_kernel<<<tgrid, tblk>>>(W_beta, p_wb);
    transpose_kernel<<<tgrid, tblk>>>(W_ctx, p_wc);

    // 1) ctx_norm (fp16)
    rms_kernel<<<Mrows, 256>>>(ctx, gr, p_norm);

    // 2) fused alpha+beta GEMM + gate epilogue -> alphas (p_a), x (p_x)
    dim3 ggrid(Ddim / 128, Mrows / 128);  // (8, 128)
    gemm_mma<true><<<ggrid, 512, SMEMF>>>(p_norm, p_wa, p_wb, b_alpha, b_beta,
                                          v, p_a, p_x);

    // 3) linear recurrence over L
    dim3 sgrid(Ddim / 256, NCHUNK, Bdim);
    scan_p1<<<sgrid, 256>>>(p_a, p_x, p_X, p_A);
    scan_p2<<<(Bdim * Ddim) / 256, 256>>>(p_X, p_A, p_c);
    scan_p3<<<sgrid, 256>>>(p_a, p_x, p_c, outp, p_f, o_out);

    // 4) ctx residual GEMM (fused bias+silu+add)
    gemm_mma<false><<<ggrid, 256, SMEMS>>>(p_f, p_wc, nullptr, b_ctx, nullptr,
                                           ctx, o_ctx, nullptr);
}

// round 7
// speedup vs baseline: 1.6812x; 1.1048x over previous
#include <cuda_runtime.h>
#include <cuda_fp16.h>
#include <cstdint>

// Problem shape (fixed by the dataset)
#define Bdim 4
#define Ldim 4096
#define Ddim 1024
#define Mrows (Bdim * Ldim)          // 16384
#define BLD ((size_t)Bdim * Ldim * Ddim)
#define NCHUNK 64
#define CLEN (Ldim / NCHUNK)         // 64
#define KDIM 1024
#define BKT 64
#define NKT (KDIM / BKT)             // 16
#define RS 72                        // smem row stride in halves (LDSM conflict-free)
#define TILE_H (128 * RS)            // halves per smem tile (9216)

// ---------------- scratch (static device arrays; no allocation) -------------
__device__ __half g_norm[(size_t)Mrows * Ddim];  // ctx_norm (fp16)
__device__ float  g_alpha[(size_t)Mrows * Ddim]; // alphas (fp32 for scan precision)
__device__ float  g_x[(size_t)Mrows * Ddim];     // gated recurrence input x_t
__device__ __half g_f[(size_t)Mrows * Ddim];     // fetched (fp16, GEMM3 input)
__device__ float  g_Xagg[(size_t)Bdim * NCHUNK * Ddim];
__device__ float  g_Aagg[(size_t)Bdim * NCHUNK * Ddim];
__device__ float  g_carry[(size_t)Bdim * NCHUNK * Ddim];
__device__ __half g_Wt[3][(size_t)Ddim * Ddim];  // transposed fp16 weights [N][K]

__device__ __forceinline__ float sigmoidf_(float z) {
    return 1.0f / (1.0f + __expf(-z));
}
__device__ __forceinline__ uint32_t smem_u32(const void* p) {
    return (uint32_t)__cvta_generic_to_shared(p);
}
#define CP16(dst, src) \
    asm volatile("cp.async.cg.shared.global [%0], [%1], 16;\n" ::"r"(dst), "l"(src))
#define LDSM4(r0, r1, r2, r3, a)                                             \
    asm volatile("ldmatrix.sync.aligned.m8n8.x4.shared.b16 {%0,%1,%2,%3}, [%4];" \
                 : "=r"(r0), "=r"(r1), "=r"(r2), "=r"(r3) : "r"(a))

// ---------------- rmsnorm (fp16 output) --------------------------------------
__global__ void rms_kernel(const float* __restrict__ ctx,
                           const float* __restrict__ g,
                           __half* __restrict__ o) {
    int row = blockIdx.x, tid = threadIdx.x;
    const float4* src = (const float4*)(ctx + (size_t)row * Ddim);
    float4 xv = src[tid];
    float ss = xv.x * xv.x + xv.y * xv.y + xv.z * xv.z + xv.w * xv.w;
#pragma unroll
    for (int off = 16; off > 0; off >>= 1)
        ss += __shfl_xor_sync(0xffffffffu, ss, off);
    __shared__ float ws[8];
    if ((tid & 31) == 0) ws[tid >> 5] = ss;
    __syncthreads();
    float tot = ws[0] + ws[1] + ws[2] + ws[3] + ws[4] + ws[5] + ws[6] + ws[7];
    float r = rsqrtf(tot * (1.0f / Ddim) + 1e-6f);
    float4 gv = ((const float4*)g)[tid];
    __half2 h01 = __floats2half2_rn(xv.x * r * gv.x, xv.y * r * gv.y);
    __half2 h23 = __floats2half2_rn(xv.z * r * gv.z, xv.w * r * gv.w);
    __half2* dst = (__half2*)(o + (size_t)row * Ddim);
    dst[tid * 2] = h01;
    dst[tid * 2 + 1] = h23;
}

// ---------------- weight transpose ([K,N] fp32 -> [N,K] fp16) ----------------
__global__ void transpose_kernel(const float* __restrict__ W, __half* __restrict__ Wt) {
    __shared__ float tile[32][33];
    int x = blockIdx.x * 32 + threadIdx.x;
    int y = blockIdx.y * 32 + threadIdx.y;
#pragma unroll
    for (int j = 0; j < 32; j += 8)
        tile[threadIdx.y + j][threadIdx.x] = W[(size_t)(y + j) * Ddim + x];
    __syncthreads();
    int nx = blockIdx.y * 32 + threadIdx.x;
    int ny = blockIdx.x * 32 + threadIdx.y;
#pragma unroll
    for (int j = 0; j < 32; j += 8)
        Wt[(size_t)(ny + j) * Ddim + nx] = __float2half_rn(tile[threadIdx.x][threadIdx.y + j]);
}

// ================= FP16 mma.sync GEMM (m16n8k16, ldmatrix, BKT=64) ===========
// SMEM tiles K-minor: T[row][k], row stride RS=72 halves (144 B).
// B stored [n][k] == col-major B -> NON-trans ldmatrix gives the B fragment.
// FUSED (512 thr): warpgroup 0 -> C1 = A*W1t, warpgroup 1 -> C2 = A*W2t
//   gate epilogue: a = sigmoid(C1+b1); beta = silu(C2+b2);
//     out1 = a; out2 = aux * beta * sqrt(max(1-a^2,1e-6)); out_v = aux (copy)
// !FUSED (256 thr): out1 = aux + silu(C1 + b1)
template <bool FUSED>
__global__ void __launch_bounds__(FUSED ? 512 : 256, FUSED ? 1 : 2) gemm_mma(
    const __half* __restrict__ A, const __half* __restrict__ W1t,
    const __half* __restrict__ W2t,
    const float* __restrict__ bias1, const float* __restrict__ bias2,
    const float* __restrict__ aux,
    float* __restrict__ out1, float* __restrict__ out2,
    float* __restrict__ out_v) {
    constexpr int NT = FUSED ? 512 : 256;
    constexpr int NTILES = FUSED ? 3 : 2;
    constexpr int STAGE_H = NTILES * TILE_H;
    extern __shared__ __half smh[];

    const int tid = threadIdx.x;
    const int warp = tid >> 5, lane = tid & 31;
    const int wg = FUSED ? (warp >> 3) : 0;   // warpgroup (0/1)
    const int w8 = warp & 7;
    const int wm = w8 >> 1, wn = w8 & 1;      // 4x2 warp grid over 128x128
    const int gid = lane >> 2, tig = lane & 3;
    const int m0 = blockIdx.y * 128, n0 = blockIdx.x * 128;

    float acc[2][8][4];
#pragma unroll
    for (int i = 0; i < 2; i++)
#pragma unroll
        for (int j = 0; j < 8; j++)
#pragma unroll
            for (int k = 0; k < 4; k++) acc[i][j][k] = 0.0f;

    // ---- ldmatrix lane-address offsets (halves, relative to tile, excl. ko)
    const int lq = lane >> 3, lr = lane & 7;
    uint32_t a_loff[2], b_loff[4];
#pragma unroll
    for (int mf = 0; mf < 2; mf++)  // A: mats (m0-7,k0-7),(m8-15,k0-7),(m0-7,k8-15),(m8-15,k8-15)
        a_loff[mf] = (uint32_t)((wm * 32 + mf * 16 + lr + (lq & 1) * 8) * RS +
                                (lq >> 1) * 8);
#pragma unroll
    for (int p = 0; p < 4; p++)     // B: mats (n0-7,k0-7),(n0-7,k8-15),(n8-15,k0-7),(n8-15,k8-15)
        b_loff[p] = (uint32_t)((wn * 64 + p * 16 + lr + (lq >> 1) * 8) * RS +
                               (lq & 1) * 8);

    // 1024 16B-chunks per tile (128 rows x 8 chunks of 8 halves)
    auto ld_tile = [&](const __half* gsrc, __half* sdst, int row_off, int k0) {
#pragma unroll
        for (int j = 0; j < 1024 / NT; j++) {
            int i = tid + j * NT;
            int row = i >> 3, c = i & 7;
            CP16(smem_u32(sdst + row * RS + c * 8),
                 gsrc + (size_t)(row_off + row) * KDIM + k0 + c * 8);
        }
    };
    auto load_stage = [&](int kt, int s) {
        const int k0 = kt * BKT;
        __half* sb = smh + s * STAGE_H;
        ld_tile(A, sb, m0, k0);
        ld_tile(W1t, sb + TILE_H, n0, k0);
        if (FUSED) ld_tile(W2t, sb + 2 * TILE_H, n0, k0);
        asm volatile("cp.async.commit_group;\n");
    };

    load_stage(0, 0);
    load_stage(1, 1);

    const uint32_t smbase = smem_u32(smh);
    int s = 0;
    for (int kt = 0; kt < NKT; kt++) {
        if (kt >= NKT - 1)
            asm volatile("cp.async.wait_group 0;\n");
        else
            asm volatile("cp.async.wait_group 1;\n");
        __syncthreads();
        if (kt + 2 < NKT) {
            int s2 = s + 2;
            if (s2 >= 3) s2 -= 3;
            load_stage(kt + 2, s2);
        }

        const uint32_t a_base = smbase + s * (STAGE_H * 2);
        const uint32_t b_base = a_base + (1 + wg) * (TILE_H * 2);
#pragma unroll
        for (int ks = 0; ks < 4; ks++) {
            const int ko2 = ks * 32;  // k offset in bytes (16 halves)
            uint32_t af[2][4];
#pragma unroll
            for (int mf = 0; mf < 2; mf++)
                LDSM4(af[mf][0], af[mf][1], af[mf][2], af[mf][3],
                      a_base + a_loff[mf] * 2 + ko2);
#pragma unroll
            for (int p = 0; p < 4; p++) {
                uint32_t b0, b1, b2, b3;
                LDSM4(b0, b1, b2, b3, b_base + b_loff[p] * 2 + ko2);
#pragma unroll
                for (int mf = 0; mf < 2; mf++) {
                    asm volatile(
                        "mma.sync.aligned.m16n8k16.row.col.f32.f16.f16.f32 "
                        "{%0,%1,%2,%3}, {%4,%5,%6,%7}, {%8,%9}, {%0,%1,%2,%3};\n"
                        : "+f"(acc[mf][2 * p][0]), "+f"(acc[mf][2 * p][1]),
                          "+f"(acc[mf][2 * p][2]), "+f"(acc[mf][2 * p][3])
                        : "r"(af[mf][0]), "r"(af[mf][1]), "r"(af[mf][2]),
                          "r"(af[mf][3]), "r"(b0), "r"(b1));
                    asm volatile(
                        "mma.sync.aligned.m16n8k16.row.col.f32.f16.f16.f32 "
                        "{%0,%1,%2,%3}, {%4,%5,%6,%7}, {%8,%9}, {%0,%1,%2,%3};\n"
                        : "+f"(acc[mf][2 * p + 1][0]), "+f"(acc[mf][2 * p + 1][1]),
                          "+f"(acc[mf][2 * p + 1][2]), "+f"(acc[mf][2 * p + 1][3])
                        : "r"(af[mf][0]), "r"(af[mf][1]), "r"(af[mf][2]),
                          "r"(af[mf][3]), "r"(b2), "r"(b3));
                }
            }
        }
        if (++s == 3) s = 0;
    }

    // ---------------- epilogue ----------------
    if (FUSED) {
        // exchange: wg1 (beta) acc -> smem, wg0 reads and applies the gate
        __syncthreads();
        float* ex = (float*)smh;  // 128x132 fp32 (67.5 KB)
        if (wg == 1) {
#pragma unroll
            for (int mf = 0; mf < 2; mf++)
#pragma unroll
                for (int nf = 0; nf < 8; nf++) {
                    int row = wm * 32 + mf * 16 + gid;
                    int col = wn * 64 + nf * 8 + tig * 2;
#pragma unroll
                    for (int h = 0; h < 2; h++) {
                        ex[(row + h * 8) * 132 + col] = acc[mf][nf][h * 2];
                        ex[(row + h * 8) * 132 + col + 1] = acc[mf][nf][h * 2 + 1];
                    }
                }
        }
        __syncthreads();
        if (wg == 0) {
#pragma unroll
            for (int mf = 0; mf < 2; mf++)
#pragma unroll
                for (int nf = 0; nf < 8; nf++) {
                    int rowl = wm * 32 + mf * 16 + gid;
                    int col = wn * 64 + nf * 8 + tig * 2;
#pragma unroll
                    for (int h = 0; h < 2; h++) {
                        int rl = rowl + h * 8;
                        size_t idx = (size_t)(m0 + rl) * Ddim + n0 + col;
                        float a0 = sigmoidf_(acc[mf][nf][h * 2] + bias1[n0 + col]);
                        float a1 = sigmoidf_(acc[mf][nf][h * 2 + 1] + bias1[n0 + col + 1]);
                        float zb0 = ex[rl * 132 + col] + bias2[n0 + col];
                        float zb1 = ex[rl * 132 + col + 1] + bias2[n0 + col + 1];
                        float be0 = zb0 * sigmoidf_(zb0);
                        float be1 = zb1 * sigmoidf_(zb1);
                        float w0 = sqrtf(fmaxf(1.0f - a0 * a0, 1e-6f));
                        float w1 = sqrtf(fmaxf(1.0f - a1 * a1, 1e-6f));
                        float2 vv = *(const float2*)(aux + idx);
                        *(float2*)(out1 + idx) = make_float2(a0, a1);
                        *(float2*)(out2 + idx) =
                            make_float2(vv.x * be0 * w0, vv.y * be1 * w1);
                        *(float2*)(out_v + idx) = vv;  // fused v pass-through
                    }
                }
        }
    } else {
#pragma unroll
        for (int mf = 0; mf < 2; mf++)
#pragma unroll
            for (int nf = 0; nf < 8; nf++) {
                int rowl = wm * 32 + mf * 16 + gid;
                int col = wn * 64 + nf * 8 + tig * 2;
#pragma unroll
                for (int h = 0; h < 2; h++) {
                    int rl = rowl + h * 8;
                    size_t idx = (size_t)(m0 + rl) * Ddim + n0 + col;
                    float z0 = acc[mf][nf][h * 2] + bias1[n0 + col];
                    float z1 = acc[mf][nf][h * 2 + 1] + bias1[n0 + col + 1];
                    float2 cv = *(const float2*)(aux + idx);
                    *(float2*)(out1 + idx) = make_float2(
                        cv.x + z0 * sigmoidf_(z0), cv.y + z1 * sigmoidf_(z1));
                }
            }
    }
}

// ---------------- chunked linear recurrence (h_t = a_t h_{t-1} + x_t) --------
__global__ void scan_p1(const float* __restrict__ a, const float* __restrict__ x,
                        float* __restrict__ Xagg, float* __restrict__ Aagg) {
    int d = blockIdx.x * blockDim.x + threadIdx.x;
    int c = blockIdx.y, b = blockIdx.z;
    size_t base = ((size_t)b * Ldim + (size_t)c * CLEN) * Ddim + d;
    float X = 0.0f, A = 1.0f;
#pragma unroll 8
    for (int t = 0; t < CLEN; t++) {
        float at = a[base + (size_t)t * Ddim];
        float xt = x[base + (size_t)t * Ddim];
        X = fmaf(at, X, xt);
        A *= at;
    }
    size_t o = ((size_t)b * NCHUNK + c) * Ddim + d;
    Xagg[o] = X;
    Aagg[o] = A;
}

__global__ void scan_p2(const float* __restrict__ Xagg,
                        const float* __restrict__ Aagg,
                        float* __restrict__ carry) {
    int i = blockIdx.x * blockDim.x + threadIdx.x;
    int b = i / Ddim, d = i % Ddim;
    float h = 0.0f;
#pragma unroll 8
    for (int c = 0; c < NCHUNK; c++) {
        size_t o = ((size_t)b * NCHUNK + c) * Ddim + d;
        carry[o] = h;
        h = fmaf(Aagg[o], h, Xagg[o]);
    }
}

__global__ void scan_p3(const float* __restrict__ a, const float* __restrict__ x,
                        const float* __restrict__ carry,
                        const float* __restrict__ out_in,
                        __half* __restrict__ f, float* __restrict__ out_out) {
    int d = blockIdx.x * blockDim.x + threadIdx.x;
    int c = blockIdx.y, b = blockIdx.z;
    size_t base = ((size_t)b * Ldim + (size_t)c * CLEN) * Ddim + d;
    size_t o = ((size_t)b * NCHUNK + c) * Ddim + d;
    float h = carry[o];
#pragma unroll 8
    for (int t = 0; t < CLEN; t++) {
        size_t i = base + (size_t)t * Ddim;
        h = fmaf(a[i], h, x[i]);
        f[i] = __float2half_rn(h);  // GEMM3 input (fp16)
        out_out[i] = out_in[i] + h; // exact residual
    }
}

// ---------------- launch ------------------------------------------------------
extern "C" void kernel_launch(void* const* d_in, const int* in_sizes, int n_in,
                              void* d_out, int out_size) {
    const float* v       = (const float*)d_in[0];
    const float* ctx     = (const float*)d_in[1];
    const float* outp    = (const float*)d_in[2];
    const float* al      = (const float*)d_in[3];
    const float* gr      = (const float*)d_in[4];
    const float* W_alpha = (const float*)d_in[5];
    const float* b_alpha = (const float*)d_in[6];
    const float* W_beta  = (const float*)d_in[7];
    const float* b_beta  = (const float*)d_in[8];
    const float* W_ctx   = (const float*)d_in[9];
    const float* b_ctx   = (const float*)d_in[10];

    float* o_v   = (float*)d_out;
    float* o_ctx = o_v + BLD;
    float* o_out = o_ctx + BLD;
    float* o_al  = o_out + BLD;

    __half *p_norm, *p_f, *p_W;
    float *p_a, *p_x, *p_X, *p_A, *p_c;
    cudaGetSymbolAddress((void**)&p_norm, g_norm);
    cudaGetSymbolAddress((void**)&p_a, g_alpha);
    cudaGetSymbolAddress((void**)&p_x, g_x);
    cudaGetSymbolAddress((void**)&p_f, g_f);
    cudaGetSymbolAddress((void**)&p_X, g_Xagg);
    cudaGetSymbolAddress((void**)&p_A, g_Aagg);
    cudaGetSymbolAddress((void**)&p_c, g_carry);
    cudaGetSymbolAddress((void**)&p_W, g_Wt);
    __half* p_wa = p_W;
    __half* p_wb = p_W + (size_t)Ddim * Ddim;
    __half* p_wc = p_W + 2 * (size_t)Ddim * Ddim;

    const int SMEMF = 3 * 3 * TILE_H * 2;  // 165888 B
    const int SMEMS = 3 * 2 * TILE_H * 2;  // 110592 B
    cudaFuncSetAttribute(gemm_mma<true>,
                         cudaFuncAttributeMaxDynamicSharedMemorySize, SMEMF);
    cudaFuncSetAttribute(gemm_mma<false>,
                         cudaFuncAttributeMaxDynamicSharedMemorySize, SMEMS);

    // alpha_logits pass-through (v pass-through is fused into the GEMM epilogue)
    cudaMemcpyAsync(o_al, al, BLD * sizeof(float), cudaMemcpyDeviceToDevice, 0);

    // weight transposes (fp16, [N][K])
    dim3 tgrid(Ddim / 32, Ddim / 32), tblk(32, 8);
    transpose_kernel<<<tgrid, tblk>>>(W_alpha, p_wa);
    transpose_kernel<<<tgrid, tblk>>>(W_beta, p_wb);
    transpose_kernel<<<tgrid, tblk>>>(W_ctx, p_wc);

    // 1) ctx_norm (fp16)
    rms_kernel<<<Mrows, 256>>>(ctx, gr, p_norm);

    // 2) fused alpha+beta GEMM + gate epilogue -> alphas (p_a), x (p_x), o_v
    dim3 ggrid(Ddim / 128, Mrows / 128);  // (8, 128)
    gemm_mma<true><<<ggrid, 512, SMEMF>>>(p_norm, p_wa, p_wb, b_alpha, b_beta,
                                          v, p_a, p_x, o_v);

    // 3) linear recurrence over L
    dim3 sgrid(Ddim / 256, NCHUNK, Bdim);
    scan_p1<<<sgrid, 256>>>(p_a, p_x, p_X, p_A);
    scan_p2<<<(Bdim * Ddim) / 256, 256>>>(p_X, p_A, p_c);
    scan_p3<<<sgrid, 256>>>(p_a, p_x, p_c, outp, p_f, o_out);

    // 4) ctx residual GEMM (fused bias+silu+add)
    gemm_mma<false><<<ggrid, 256, SMEMS>>>(p_f, p_wc, nullptr, b_ctx, nullptr,
                                           ctx, o_ctx, nullptr, nullptr);
}